// round 12
// baseline (speedup 1.0000x reference)
#include <cuda_runtime.h>
#include <cuda_fp16.h>
#include <cstdint>

typedef unsigned u32;

#define NAGENT 8
#define BATCH  32768
#define BM     64

// ---- scratch: fragment-major fp16 weights ----
// per agent (stride 94208 B): L1+aux frags 0..175 (tiles 0..21), L2 frags 176..303,
// L3 frags 304..367. frag = tile*8 + kt; entry = frag*256 + lane*8 (uint2 per lane).
#define AGSTRIDE 94208
#define L2_OFF_U2 5632    // 176*256/8
#define L3_OFF_U2 9728    // 304*256/8
__device__ __align__(16) unsigned char g_w[8 * AGSTRIDE];

// ---- smem byte offsets (per CTA, ~66 KB -> 2 CTAs/SM) ----
#define RA    0          // plane P0: 64 rows x 256B fp16
#define RB    16384      // plane P1
#define RST   32768      // f32 states staging (64 x 512B = 32KB)
#define SGOFF 65536      // gate per row (64 f32)
#define SREDO 65792      // csum partials (64 rows x 2 slots)
#define SMEM_TOTAL 66304

// ======================= helpers =======================
__device__ __forceinline__ u32 smem_u32(const void* p) {
    u32 a; asm("{ .reg .u64 t; cvta.to.shared.u64 t, %1; cvt.u32.u64 %0, t; }" : "=r"(a) : "l"(p));
    return a;
}
__device__ __forceinline__ void cp16(u32 dst, const void* src) {
    asm volatile("cp.async.cg.shared.global [%0], [%1], 16;" :: "r"(dst), "l"(src));
}
__device__ __forceinline__ void cp_commit() { asm volatile("cp.async.commit_group;"); }
template<int N> __device__ __forceinline__ void cp_wait() {
    asm volatile("cp.async.wait_group %0;" :: "n"(N) : "memory");
}
__device__ __forceinline__ u32 pack_h(float x, float y) {
    __half2 h = __floats2half2_rn(x, y);
    return *reinterpret_cast<u32*>(&h);
}
// activation plane byte offset: row n, half-col k; 256B rows, XOR swizzle on 16B chunks
__device__ __forceinline__ u32 plane_off(int n, int k) {
    int c = k >> 3;
    u32 sw = (u32)(((c ^ n) & 7) | (c & 8));
    return (u32)(n * 256) + (sw << 4) + (u32)((k & 7) * 2);
}
__device__ __forceinline__ void ldm4(u32* a, u32 addr) {
    asm volatile("ldmatrix.sync.aligned.m8n8.x4.shared.b16 {%0,%1,%2,%3}, [%4];"
        : "=r"(a[0]), "=r"(a[1]), "=r"(a[2]), "=r"(a[3]) : "r"(addr));
}
__device__ __forceinline__ void mma_h(float* d, const u32* a, const u32* b) {
    asm volatile("mma.sync.aligned.m16n8k16.row.col.f32.f16.f16.f32 "
        "{%0,%1,%2,%3}, {%4,%5,%6,%7}, {%8,%9}, {%0,%1,%2,%3};"
        : "+f"(d[0]), "+f"(d[1]), "+f"(d[2]), "+f"(d[3])
        : "r"(a[0]), "r"(a[1]), "r"(a[2]), "r"(a[3]), "r"(b[0]), "r"(b[1]));
}
__device__ __forceinline__ uint2 ldg_v2(const uint2* p) {
    uint2 r; asm("ld.global.nc.v2.u32 {%0,%1}, [%2];" : "=r"(r.x), "=r"(r.y) : "l"(p));
    return r;
}

// convert own-copied f32 chunks (RST) -> fp16 plane. Each thread touches exactly
// the bytes it cp.async'd (same tid*16 + 4096j mapping) => only own-group wait needed.
__device__ __forceinline__ void convert_own(u32 sb, u32 dst, int tid) {
#pragma unroll
    for (int j = 0; j < 8; j++) {
        int o = tid * 16 + 4096 * j;
        int m = o >> 9, c4 = (o & 511) >> 4;
        float4 v;
        asm volatile("ld.shared.v4.f32 {%0,%1,%2,%3}, [%4];"
            : "=f"(v.x), "=f"(v.y), "=f"(v.z), "=f"(v.w) : "r"(sb + RST + o));
        u32 h0 = pack_h(v.x, v.y);
        u32 h1 = pack_h(v.z, v.w);
        asm volatile("st.shared.v2.b32 [%0], {%1,%2};"
            :: "r"(dst + plane_off(m, c4 * 4)), "r"(h0), "r"(h1));
    }
}

// ============ warp GEMM: 32 M-rows, NF n8-tiles; A from smem, B fragments from global ====
// wl = fragment base for this layer, already offset by +lane (uint2 units; 32 per frag)
template<int NF>
__device__ __forceinline__ void gemm2m(float C[2][NF][4], u32 ah,
                                       const uint2* __restrict__ wl,
                                       int m0, int tbase, int lane)
{
#pragma unroll
    for (int mf = 0; mf < 2; mf++)
#pragma unroll
        for (int j = 0; j < NF; j++)
#pragma unroll
            for (int i = 0; i < 4; i++) C[mf][j][i] = 0.f;

    const int rA = m0 + (lane & 7) + ((lane >> 3) & 1) * 8;
    const int gA = lane >> 4;
    const u32 oA = (u32)rA * 256;

#pragma unroll
    for (int t = 0; t < 8; t++) {
        const int cA = 2 * t + gA;
        const u32 swA = ((u32)(((cA ^ rA) & 7) | (cA & 8))) << 4;
        u32 A0[4], A1[4];
        ldm4(A0, ah + oA + swA);            // rows m0..m0+15
        ldm4(A1, ah + oA + 4096 + swA);     // rows m0+16..m0+31

        uint2 b[NF];
#pragma unroll
        for (int j = 0; j < NF; j++)
            b[j] = ldg_v2(wl + ((tbase + j) * 8 + t) * 32);
#pragma unroll
        for (int j = 0; j < NF; j++) {
            u32 B2[2] = { b[j].x, b[j].y };
            mma_h(C[0][j], A0, B2);
            mma_h(C[1][j], A1, B2);
        }
    }
}

// ======================= L1 epilogue (activation stores to dst + aux) =======================
template<int NF, int TBASE>
__device__ __forceinline__ void epi_L1(float C[2][NF][4], u32 dst,
    const float* __restrict__ b1n, const float* __restrict__ bc1,
    const float* __restrict__ Wc2,
    float r_bs1, float r_Ws2, float r_bs2, float r_bc2,
    float* sG, float creg[4], int m0, int lane, int q)
{
    float cp[4] = {0.f, 0.f, 0.f, 0.f};
#pragma unroll
    for (int j = 0; j < NF; j++) {
        const int tile = TBASE + j;
        if (tile < 16) {
            int col = tile * 8 + q;
            float bx = __ldg(b1n + col), by = __ldg(b1n + col + 1);
#pragma unroll
            for (int mf = 0; mf < 2; mf++) {
                int row0 = m0 + mf * 16 + (lane >> 2), row8 = row0 + 8;
                u32 h0 = pack_h(fmaxf(C[mf][j][0] + bx, 0.f), fmaxf(C[mf][j][1] + by, 0.f));
                u32 h2 = pack_h(fmaxf(C[mf][j][2] + bx, 0.f), fmaxf(C[mf][j][3] + by, 0.f));
                u32 sw0 = ((u32)(((tile ^ row0) & 7) | (tile & 8))) << 4;
                u32 sw8 = ((u32)(((tile ^ row8) & 7) | (tile & 8))) << 4;
                asm volatile("st.shared.b32 [%0], %1;"
                    :: "r"(dst + (u32)row0 * 256 + sw0 + (u32)(q * 2)), "r"(h0));
                asm volatile("st.shared.b32 [%0], %1;"
                    :: "r"(dst + (u32)row8 * 256 + sw8 + (u32)(q * 2)), "r"(h2));
            }
        } else if (tile < 20) {     // constraint cols: e in [0,32)
            int e = (tile - 16) * 8 + q;
            float bb0 = __ldg(bc1 + e),  bb1 = __ldg(bc1 + e + 1);
            float w0  = __ldg(Wc2 + e),  w1  = __ldg(Wc2 + e + 1);
#pragma unroll
            for (int mf = 0; mf < 2; mf++) {
                cp[mf * 2 + 0] = fmaf(fmaxf(C[mf][j][0] + bb0, 0.f), w0,
                                 fmaf(fmaxf(C[mf][j][1] + bb1, 0.f), w1, cp[mf * 2 + 0]));
                cp[mf * 2 + 1] = fmaf(fmaxf(C[mf][j][2] + bb0, 0.f), w0,
                                 fmaf(fmaxf(C[mf][j][3] + bb1, 0.f), w1, cp[mf * 2 + 1]));
            }
        } else if (tile == 20) {    // gate col (e==32) at q==0
            if (q == 0) {
#pragma unroll
                for (int mf = 0; mf < 2; mf++) {
                    int row0 = m0 + mf * 16 + (lane >> 2), row8 = row0 + 8;
                    float s0 = fmaf(fmaxf(C[mf][j][0] + r_bs1, 0.f), r_Ws2, r_bs2);
                    float s8 = fmaf(fmaxf(C[mf][j][2] + r_bs1, 0.f), r_Ws2, r_bs2);
                    sG[row0] = 1.f / (1.f + __expf(-s0));
                    sG[row8] = 1.f / (1.f + __expf(-s8));
                }
            }
        }
        // tile 21: zero padding, skip
    }
    if (TBASE >= 12) {              // constraint-carrying warps (nw 2,3)
#pragma unroll
        for (int i = 0; i < 4; i++) {
            cp[i] += __shfl_xor_sync(0xffffffffu, cp[i], 1);
            cp[i] += __shfl_xor_sync(0xffffffffu, cp[i], 2);
        }
        if ((lane & 3) == 0) {
            float add = (TBASE == 12) ? r_bc2 : 0.f;
#pragma unroll
            for (int i = 0; i < 4; i++) creg[i] += cp[i] + add;
        }
    }
}

// ====== prep kernel: fp32 weights -> fragment-major fp16 (mma.sync B layout) ======
extern "C" __global__ void __launch_bounds__(256)
prep_kernel(const float* __restrict__ W1, const float* __restrict__ W2,
            const float* __restrict__ W3, const float* __restrict__ Wc1,
            const float* __restrict__ Ws1)
{
    int idx = blockIdx.x * 256 + threadIdx.x;
    if (idx >= 8 * 11776) return;
    int agent = idx / 11776;
    int e = idx % 11776;
    int frag = e >> 5;
    int lane = e & 31;
    int nlow = lane >> 2, klow = (lane & 3) * 2;

    float w00, w01, w10, w11;
    if (frag < 176) {
        int tile = frag >> 3, kt = frag & 7;
        int k0 = kt * 16 + klow;
        if (tile < 16) {
            const float* src = W1 + agent * 16384;
            int n = tile * 8 + nlow;
            w00 = src[k0 * 128 + n];       w01 = src[(k0 + 1) * 128 + n];
            w10 = src[(k0 + 8) * 128 + n]; w11 = src[(k0 + 9) * 128 + n];
        } else {
            int c = (tile - 16) * 8 + nlow;   // aux col: 0..31 Wc1^T, 32 Ws1, else 0
            auto aux = [&](int k) -> float {
                if (c < 32)  return __ldg(Wc1 + k * 32 + c);
                if (c == 32) return __ldg(Ws1 + k);
                return 0.f;
            };
            w00 = aux(k0);     w01 = aux(k0 + 1);
            w10 = aux(k0 + 8); w11 = aux(k0 + 9);
        }
    } else if (frag < 304) {
        int f = frag - 176;
        int tile = f >> 3, kt = f & 7;
        int k0 = kt * 16 + klow;
        const float* src = W2 + agent * 16384;
        int n = tile * 8 + nlow;
        w00 = src[k0 * 128 + n];       w01 = src[(k0 + 1) * 128 + n];
        w10 = src[(k0 + 8) * 128 + n]; w11 = src[(k0 + 9) * 128 + n];
    } else {
        int f = frag - 304;
        int tile = f >> 3, kt = f & 7;
        int k0 = kt * 16 + klow;
        const float* src = W3 + agent * 8192;
        int n = tile * 8 + nlow;
        w00 = src[k0 * 64 + n];       w01 = src[(k0 + 1) * 64 + n];
        w10 = src[(k0 + 8) * 64 + n]; w11 = src[(k0 + 9) * 64 + n];
    }
    uint2 v = make_uint2(pack_h(w00, w01), pack_h(w10, w11));
    *(uint2*)(g_w + (size_t)agent * AGSTRIDE + (size_t)frag * 256 + lane * 8) = v;
}

// ======================= main kernel =======================
extern "C" __global__ void __launch_bounds__(256, 2)
qatten_mma(const float* __restrict__ states,
           const float* __restrict__ b1, const float* __restrict__ b2,
           const float* __restrict__ b3,
           const float* __restrict__ bs1, const float* __restrict__ Ws2,
           const float* __restrict__ bs2,
           const float* __restrict__ bc1, const float* __restrict__ Wc2,
           const float* __restrict__ bc2,
           float* __restrict__ out)
{
    extern __shared__ char smem[];
    const u32 sb = smem_u32(smem);
    const int tid = threadIdx.x;
    const int wid = tid >> 5, lane = tid & 31;
    const int b0 = blockIdx.x * BM;

    const int mq = wid & 1, nw = wid >> 1;   // 2 M-slices x 4 N-slices
    const int m0 = mq * 32;
    const int q = (lane & 3) * 2;

    float* sG  = (float*)(smem + SGOFF);
    float* sRd = (float*)(smem + SREDO);

    // ---- prologue: stage states(0) -> RST; convert -> P0 ----
    {
        const unsigned char* S0 = (const unsigned char*)(states + (size_t)b0 * 128);
        for (int i = tid * 16; i < 32768; i += 4096) cp16(sb + RST + i, S0 + i);
        cp_commit();
        cp_wait<0>();
        convert_own(sb, sb + RA, tid);   // states(0) -> P0
    }

    float oacc[2][2][4];
#pragma unroll
    for (int mf = 0; mf < 2; mf++)
#pragma unroll
        for (int j = 0; j < 2; j++)
#pragma unroll
            for (int i = 0; i < 4; i++) oacc[mf][j][i] = 0.f;
    float creg[4] = {0.f, 0.f, 0.f, 0.f};
    const float r_bs1 = __ldg(bs1), r_Ws2 = __ldg(Ws2), r_bs2 = __ldg(bs2), r_bc2 = __ldg(bc2);

    for (int n = 0; n < NAGENT; n++) {
        const u32 pin  = sb + ((n & 1) ? RB : RA);   // L1 input (states), L2 output, L3 input
        const u32 pmid = sb + ((n & 1) ? RA : RB);   // L1 output, L2 input, convert(n+1) dest
        const uint2* wl = (const uint2*)(g_w + (size_t)n * AGSTRIDE) + lane;

        // ---- sync1: convert(n) visible to all warps ----
        __syncthreads();

        // ---- L1 + aux: pin @ [W1 ; Wc1^T ; Ws1] (tiles 0..21) -> pmid, sG, creg ----
        {
            const float* b1n = b1 + n * 128;
            if (nw < 2) {
                float C[2][6][4];
                gemm2m<6>(C, pin, wl, m0, nw * 6, lane);
                if (nw == 0)
                    epi_L1<6, 0>(C, pmid, b1n, bc1, Wc2, r_bs1, r_Ws2, r_bs2, r_bc2,
                                 sG, creg, m0, lane, q);
                else
                    epi_L1<6, 6>(C, pmid, b1n, bc1, Wc2, r_bs1, r_Ws2, r_bs2, r_bc2,
                                 sG, creg, m0, lane, q);
            } else {
                float C[2][5][4];
                gemm2m<5>(C, pin, wl, m0, (nw == 2) ? 12 : 17, lane);
                if (nw == 2)
                    epi_L1<5, 12>(C, pmid, b1n, bc1, Wc2, r_bs1, r_Ws2, r_bs2, r_bc2,
                                  sG, creg, m0, lane, q);
                else
                    epi_L1<5, 17>(C, pmid, b1n, bc1, Wc2, r_bs1, r_Ws2, r_bs2, r_bc2,
                                  sG, creg, m0, lane, q);
            }
        }
        // ---- sync2: pmid writes visible before L2 reads ----
        __syncthreads();

        // ---- L2: pmid @ W2 -> pin; prefetch states(n+1) into RST ----
        {
            if (n < NAGENT - 1) {   // RST free: convert(n) done before sync1
                const unsigned char* Sn =
                    (const unsigned char*)(states + ((size_t)(n + 1) * BATCH + b0) * 128);
                for (int i = tid * 16; i < 32768; i += 4096) cp16(sb + RST + i, Sn + i);
                cp_commit();
            }
            float C[2][4][4];
            gemm2m<4>(C, pmid, wl + L2_OFF_U2, m0, nw * 4, lane);
            const float* b2n = b2 + n * 128;
#pragma unroll
            for (int j = 0; j < 4; j++) {
                int tile = nw * 4 + j;
                int col = tile * 8 + q;
                float bx = __ldg(b2n + col), by = __ldg(b2n + col + 1);
#pragma unroll
                for (int mf = 0; mf < 2; mf++) {
                    int row0 = m0 + mf * 16 + (lane >> 2), row8 = row0 + 8;
                    u32 h0 = pack_h(fmaxf(C[mf][j][0] + bx, 0.f), fmaxf(C[mf][j][1] + by, 0.f));
                    u32 h2 = pack_h(fmaxf(C[mf][j][2] + bx, 0.f), fmaxf(C[mf][j][3] + by, 0.f));
                    u32 sw0 = ((u32)(((tile ^ row0) & 7) | (tile & 8))) << 4;
                    u32 sw8 = ((u32)(((tile ^ row8) & 7) | (tile & 8))) << 4;
                    asm volatile("st.shared.b32 [%0], %1;"
                        :: "r"(pin + (u32)row0 * 256 + sw0 + (u32)(q * 2)), "r"(h0));
                    asm volatile("st.shared.b32 [%0], %1;"
                        :: "r"(pin + (u32)row8 * 256 + sw8 + (u32)(q * 2)), "r"(h2));
                }
            }
        }
        // ---- sync3: pin(L2 out) visible before L3 reads ----
        __syncthreads();

        // ---- L3: pin @ W3 -> oacc ; convert(n+1) -> pmid hides under the gemm ----
        {
            float C[2][2][4];
            gemm2m<2>(C, pin, wl + L3_OFF_U2, m0, nw * 2, lane);
            if (n < NAGENT - 1) {
                cp_wait<0>();               // own states(n+1) chunks done
                convert_own(sb, pmid, tid); // pmid free (L2 consumed it)
            }
            const float* b3n = b3 + n * 64;
#pragma unroll
            for (int mf = 0; mf < 2; mf++) {
                int row0 = m0 + mf * 16 + (lane >> 2), row8 = row0 + 8;
                float g0 = sG[row0], g8 = sG[row8];
#pragma unroll
                for (int j = 0; j < 2; j++) {
                    int col = (nw * 2 + j) * 8 + q;
                    float bx = __ldg(b3n + col), by = __ldg(b3n + col + 1);
                    oacc[mf][j][0] = fmaf(g0, C[mf][j][0] + bx, oacc[mf][j][0]);
                    oacc[mf][j][1] = fmaf(g0, C[mf][j][1] + by, oacc[mf][j][1]);
                    oacc[mf][j][2] = fmaf(g8, C[mf][j][2] + bx, oacc[mf][j][2]);
                    oacc[mf][j][3] = fmaf(g8, C[mf][j][3] + by, oacc[mf][j][3]);
                }
            }
        }
    }

    // ---- final: csum exchange + output ----
    __syncthreads();
    if ((nw == 2 || nw == 3) && (lane & 3) == 0) {
        int slot = nw - 2;
#pragma unroll
        for (int i = 0; i < 4; i++) {
            int row = m0 + (i >> 1) * 16 + (i & 1) * 8 + (lane >> 2);
            sRd[row * 2 + slot] = creg[i];
        }
    }
    __syncthreads();
#pragma unroll
    for (int mf = 0; mf < 2; mf++) {
#pragma unroll
        for (int h = 0; h < 2; h++) {
            int row = m0 + mf * 16 + h * 8 + (lane >> 2);
            float cs = (sRd[row * 2] + sRd[row * 2 + 1]) * 0.125f;
#pragma unroll
            for (int j = 0; j < 2; j++) {
                int col = (nw * 2 + j) * 8 + q;
                float2 v;
                v.x = fmaf(oacc[mf][j][2 * h + 0], 0.125f, cs);
                v.y = fmaf(oacc[mf][j][2 * h + 1], 0.125f, cs);
                *(float2*)(out + (size_t)(b0 + row) * 64 + col) = v;
            }
        }
    }
}

extern "C" void kernel_launch(void* const* d_in, const int* in_sizes, int n_in,
                              void* d_out, int out_size)
{
    const float* states = (const float*)d_in[0];
    const float* W1  = (const float*)d_in[1];
    const float* b1  = (const float*)d_in[2];
    const float* W2  = (const float*)d_in[3];
    const float* b2  = (const float*)d_in[4];
    const float* W3  = (const float*)d_in[5];
    const float* b3  = (const float*)d_in[6];
    // d_in[7..12]: Wq1,bq1,Wq2,bq2,Wk,bk — dead (softmax rows sum to 1)
    const float* Ws1 = (const float*)d_in[13];
    const float* bs1 = (const float*)d_in[14];
    const float* Ws2 = (const float*)d_in[15];
    const float* bs2 = (const float*)d_in[16];
    const float* Wc1 = (const float*)d_in[17];
    const float* bc1 = (const float*)d_in[18];
    const float* Wc2 = (const float*)d_in[19];
    const float* bc2 = (const float*)d_in[20];
    float* out = (float*)d_out;

    prep_kernel<<<(8 * 11776 + 255) / 256, 256>>>(W1, W2, W3, Wc1, Ws1);

    cudaFuncSetAttribute(qatten_mma,
                         cudaFuncAttributeMaxDynamicSharedMemorySize, SMEM_TOTAL);
    qatten_mma<<<BATCH / BM, 256, SMEM_TOTAL>>>(
        states, b1, b2, b3, bs1, Ws2, bs2, bc1, Wc2, bc2, out);
}

// round 13
// speedup vs baseline: 1.0536x; 1.0536x over previous
#include <cuda_runtime.h>
#include <cuda_fp16.h>
#include <cstdint>

typedef unsigned u32;

#define NAGENT 8
#define BATCH  32768
#define BM     64

// ---- scratch: pre-swizzled fp16 weights ----
// per agent: L1 (128 rows) off 0, L2 off 32768, L3 (64 rows) off 65536; stride 81920
__device__ __align__(16) unsigned char g_w[8 * 81920];
__device__ __align__(16) unsigned char g_ax[48 * 256];   // aux: Wc1^T rows 0-31, Ws1 row 32, pad

// ---- smem byte offsets (per CTA, ~109 KB -> 2 CTAs/SM) ----
#define RA    0          // plane P0: 64 rows x 256B fp16
#define RB    16384      // plane P1
#define RST   32768      // f32 states staging (64 x 512B = 32KB)
#define RW    65536      // weights, 176 rows x 256B = 45056 (aux rows 128-175 persist)
#define SGOFF 110592     // gate per row (64 f32)
#define SREDO 110848     // csum partials (64 rows x 2 slots)
#define SMEM_TOTAL 111616

// ======================= helpers =======================
__device__ __forceinline__ u32 smem_u32(const void* p) {
    u32 a; asm("{ .reg .u64 t; cvta.to.shared.u64 t, %1; cvt.u32.u64 %0, t; }" : "=r"(a) : "l"(p));
    return a;
}
__device__ __forceinline__ void cp16(u32 dst, const void* src) {
    asm volatile("cp.async.cg.shared.global [%0], [%1], 16;" :: "r"(dst), "l"(src));
}
__device__ __forceinline__ void cp_commit() { asm volatile("cp.async.commit_group;"); }
template<int N> __device__ __forceinline__ void cp_wait() {
    asm volatile("cp.async.wait_group %0;" :: "n"(N) : "memory");
}
__device__ __forceinline__ void pf_l2(const void* p) {
    asm volatile("prefetch.global.L2 [%0];" :: "l"(p));
}
__device__ __forceinline__ u32 pack_h(float x, float y) {
    __half2 h = __floats2half2_rn(x, y);
    return *reinterpret_cast<u32*>(&h);
}
// plane byte offset: row n, half-col k; 256B rows, XOR swizzle on 16B chunks
__device__ __forceinline__ u32 plane_off(int n, int k) {
    int c = k >> 3;
    u32 sw = (u32)(((c ^ n) & 7) | (c & 8));
    return (u32)(n * 256) + (sw << 4) + (u32)((k & 7) * 2);
}
__device__ __forceinline__ void ldm4(u32* a, u32 addr) {
    asm volatile("ldmatrix.sync.aligned.m8n8.x4.shared.b16 {%0,%1,%2,%3}, [%4];"
        : "=r"(a[0]), "=r"(a[1]), "=r"(a[2]), "=r"(a[3]) : "r"(addr));
}
__device__ __forceinline__ void ldm2(u32* b, u32 addr) {
    asm volatile("ldmatrix.sync.aligned.m8n8.x2.shared.b16 {%0,%1}, [%2];"
        : "=r"(b[0]), "=r"(b[1]) : "r"(addr));
}
__device__ __forceinline__ void mma_h(float* d, const u32* a, const u32* b) {
    asm volatile("mma.sync.aligned.m16n8k16.row.col.f32.f16.f16.f32 "
        "{%0,%1,%2,%3}, {%4,%5,%6,%7}, {%8,%9}, {%0,%1,%2,%3};"
        : "+f"(d[0]), "+f"(d[1]), "+f"(d[2]), "+f"(d[3])
        : "r"(a[0]), "r"(a[1]), "r"(a[2]), "r"(a[3]), "r"(b[0]), "r"(b[1]));
}

// convert own-copied f32 chunks (RST) -> fp16 plane. Each thread touches exactly
// the bytes it cp.async'd (same tid*16 + 4096j mapping) => only own-group wait needed.
__device__ __forceinline__ void convert_own(u32 sb, u32 dst, int tid) {
#pragma unroll
    for (int j = 0; j < 8; j++) {
        int o = tid * 16 + 4096 * j;
        int m = o >> 9, c4 = (o & 511) >> 4;
        float4 v;
        asm volatile("ld.shared.v4.f32 {%0,%1,%2,%3}, [%4];"
            : "=f"(v.x), "=f"(v.y), "=f"(v.z), "=f"(v.w) : "r"(sb + RST + o));
        u32 h0 = pack_h(v.x, v.y);
        u32 h1 = pack_h(v.z, v.w);
        asm volatile("st.shared.v2.b32 [%0], {%1,%2};"
            :: "r"(dst + plane_off(m, c4 * 4)), "r"(h0), "r"(h1));
    }
}

// ============ warp GEMM: 32 M-rows (MF=2), NF n8-tiles, paired x4 B loads ============
template<int NF>
__device__ __forceinline__ void gemm2m(float C[2][NF][4], u32 ah, u32 bw,
                                       int m0, int tbase, int lane)
{
#pragma unroll
    for (int mf = 0; mf < 2; mf++)
#pragma unroll
        for (int j = 0; j < NF; j++)
#pragma unroll
            for (int i = 0; i < 4; i++) C[mf][j][i] = 0.f;

    const int rA = m0 + (lane & 7) + ((lane >> 3) & 1) * 8;
    const int gA = lane >> 4;
    const u32 oA = (u32)rA * 256;
    const int rBl = lane & 7;
    const int gB = (lane >> 3) & 1;
    const int tsel = (lane >> 4) & 1;

#pragma unroll
    for (int t = 0; t < 8; t++) {
        const int cA = 2 * t + gA;
        const u32 swA = ((u32)(((cA ^ rA) & 7) | (cA & 8))) << 4;
        u32 A0[4], A1[4];
        ldm4(A0, ah + oA + swA);            // rows m0..m0+15
        ldm4(A1, ah + oA + 4096 + swA);     // rows m0+16..m0+31

        const int cB = 2 * t + gB;
#pragma unroll
        for (int jp = 0; jp < NF / 2; jp++) {
            int tile = tbase + 2 * jp + tsel;
            int rB = tile * 8 + rBl;
            u32 swB = ((u32)(((cB ^ rB) & 7) | (cB & 8))) << 4;
            u32 B4[4];
            ldm4(B4, bw + (u32)rB * 256 + swB);
            mma_h(C[0][2 * jp],     A0, B4);
            mma_h(C[0][2 * jp + 1], A0, B4 + 2);
            mma_h(C[1][2 * jp],     A1, B4);
            mma_h(C[1][2 * jp + 1], A1, B4 + 2);
        }
        if (NF & 1) {
            int tile = tbase + NF - 1;
            int rB = tile * 8 + rBl;
            u32 swB = ((u32)(((cB ^ rB) & 7) | (cB & 8))) << 4;
            u32 B2[2];
            ldm2(B2, bw + (u32)rB * 256 + swB);
            mma_h(C[0][NF - 1], A0, B2);
            mma_h(C[1][NF - 1], A1, B2);
        }
    }
}

// ======================= L1 epilogue (activation stores to dst + aux) =======================
template<int NF, int TBASE>
__device__ __forceinline__ void epi_L1(float C[2][NF][4], u32 dst,
    const float* __restrict__ b1n, const float* __restrict__ bc1,
    const float* __restrict__ Wc2,
    float r_bs1, float r_Ws2, float r_bs2, float r_bc2,
    float* sG, float creg[4], int m0, int lane, int q)
{
    float cp[4] = {0.f, 0.f, 0.f, 0.f};
#pragma unroll
    for (int j = 0; j < NF; j++) {
        const int tile = TBASE + j;
        if (tile < 16) {
            int col = tile * 8 + q;
            float bx = __ldg(b1n + col), by = __ldg(b1n + col + 1);
#pragma unroll
            for (int mf = 0; mf < 2; mf++) {
                int row0 = m0 + mf * 16 + (lane >> 2), row8 = row0 + 8;
                u32 h0 = pack_h(fmaxf(C[mf][j][0] + bx, 0.f), fmaxf(C[mf][j][1] + by, 0.f));
                u32 h2 = pack_h(fmaxf(C[mf][j][2] + bx, 0.f), fmaxf(C[mf][j][3] + by, 0.f));
                u32 sw0 = ((u32)(((tile ^ row0) & 7) | (tile & 8))) << 4;
                u32 sw8 = ((u32)(((tile ^ row8) & 7) | (tile & 8))) << 4;
                asm volatile("st.shared.b32 [%0], %1;"
                    :: "r"(dst + (u32)row0 * 256 + sw0 + (u32)(q * 2)), "r"(h0));
                asm volatile("st.shared.b32 [%0], %1;"
                    :: "r"(dst + (u32)row8 * 256 + sw8 + (u32)(q * 2)), "r"(h2));
            }
        } else if (tile < 20) {     // constraint cols: e in [0,32)
            int e = (tile - 16) * 8 + q;
            float bb0 = __ldg(bc1 + e),  bb1 = __ldg(bc1 + e + 1);
            float w0  = __ldg(Wc2 + e),  w1  = __ldg(Wc2 + e + 1);
#pragma unroll
            for (int mf = 0; mf < 2; mf++) {
                cp[mf * 2 + 0] = fmaf(fmaxf(C[mf][j][0] + bb0, 0.f), w0,
                                 fmaf(fmaxf(C[mf][j][1] + bb1, 0.f), w1, cp[mf * 2 + 0]));
                cp[mf * 2 + 1] = fmaf(fmaxf(C[mf][j][2] + bb0, 0.f), w0,
                                 fmaf(fmaxf(C[mf][j][3] + bb1, 0.f), w1, cp[mf * 2 + 1]));
            }
        } else if (tile == 20) {    // gate col (e==32) at q==0
            if (q == 0) {
#pragma unroll
                for (int mf = 0; mf < 2; mf++) {
                    int row0 = m0 + mf * 16 + (lane >> 2), row8 = row0 + 8;
                    float s0 = fmaf(fmaxf(C[mf][j][0] + r_bs1, 0.f), r_Ws2, r_bs2);
                    float s8 = fmaf(fmaxf(C[mf][j][2] + r_bs1, 0.f), r_Ws2, r_bs2);
                    sG[row0] = 1.f / (1.f + __expf(-s0));
                    sG[row8] = 1.f / (1.f + __expf(-s8));
                }
            }
        }
        // tile 21: zero padding, skip
    }
    if (TBASE >= 12) {              // constraint-carrying warps (nw 2,3)
#pragma unroll
        for (int i = 0; i < 4; i++) {
            cp[i] += __shfl_xor_sync(0xffffffffu, cp[i], 1);
            cp[i] += __shfl_xor_sync(0xffffffffu, cp[i], 2);
        }
        if ((lane & 3) == 0) {
            float add = (TBASE == 12) ? r_bc2 : 0.f;
#pragma unroll
            for (int i = 0; i < 4; i++) creg[i] += cp[i] + add;
        }
    }
}

// ======================= prep kernel: fp32 weights -> swizzled fp16 =======================
extern "C" __global__ void __launch_bounds__(256)
prep_kernel(const float* __restrict__ W1, const float* __restrict__ W2,
            const float* __restrict__ W3, const float* __restrict__ Wc1,
            const float* __restrict__ Ws1)
{
    int idx = blockIdx.x * 256 + threadIdx.x;
    if (idx < 81920) {
        int agent = idx / 10240;
        int rem = idx % 10240;
        int row = rem >> 5;
        int k = (rem & 31) * 4;
        const float* src; int n, N; u32 loff;
        if (row < 128)      { src = W1 + agent * 16384; n = row;       N = 128; loff = 0; }
        else if (row < 256) { src = W2 + agent * 16384; n = row - 128; N = 128; loff = 32768; }
        else                { src = W3 + agent * 8192;  n = row - 256; N = 64;  loff = 65536; }
        u32 h0 = pack_h(src[(k + 0) * N + n], src[(k + 1) * N + n]);
        u32 h1 = pack_h(src[(k + 2) * N + n], src[(k + 3) * N + n]);
        *(uint2*)(g_w + (u32)agent * 81920 + loff + plane_off(n, k)) = make_uint2(h0, h1);
    } else if (idx < 81920 + 1536) {
        int rem = idx - 81920;
        int row = rem >> 5;
        int k = (rem & 31) * 4;
        float w[4];
#pragma unroll
        for (int i = 0; i < 4; i++) {
            int kk = k + i;
            w[i] = (row < 32) ? __ldg(Wc1 + kk * 32 + row) : (row == 32 ? __ldg(Ws1 + kk) : 0.f);
        }
        *(uint2*)(g_ax + plane_off(row, k)) =
            make_uint2(pack_h(w[0], w[1]), pack_h(w[2], w[3]));
    }
}

// ======================= main kernel =======================
extern "C" __global__ void __launch_bounds__(256, 2)
qatten_mma(const float* __restrict__ states,
           const float* __restrict__ b1, const float* __restrict__ b2,
           const float* __restrict__ b3,
           const float* __restrict__ bs1, const float* __restrict__ Ws2,
           const float* __restrict__ bs2,
           const float* __restrict__ bc1, const float* __restrict__ Wc2,
           const float* __restrict__ bc2,
           float* __restrict__ out)
{
    extern __shared__ char smem[];
    const u32 sb = smem_u32(smem);
    const int tid = threadIdx.x;
    const int wid = tid >> 5, lane = tid & 31;
    const int b0 = blockIdx.x * BM;

    const int mq = wid & 1, nw = wid >> 1;   // 2 M-slices x 4 N-slices
    const int m0 = mq * 32;
    const int q = (lane & 3) * 2;

    float* sG  = (float*)(smem + SGOFF);
    float* sRd = (float*)(smem + SREDO);

    // ---- prologue: stage states(0) -> RST; W1(0)+aux -> RW; convert(0) -> P0 ----
    {
        const unsigned char* S0 = (const unsigned char*)(states + (size_t)b0 * 128);
        for (int i = tid * 16; i < 32768; i += 4096) cp16(sb + RST + i, S0 + i);
        cp_commit();                                        // [S]
        for (int i = tid * 16; i < 32768; i += 4096) cp16(sb + RW + i, g_w + i);
        for (int i = tid * 16; i < 12288; i += 4096) cp16(sb + RW + 32768 + i, g_ax + i);
        cp_commit();                                        // [S, W1]
        cp_wait<1>();                // own states chunks done (W1 outstanding)
        convert_own(sb, sb + RA, tid);   // states(0) -> P0
    }

    float oacc[2][2][4];
#pragma unroll
    for (int mf = 0; mf < 2; mf++)
#pragma unroll
        for (int j = 0; j < 2; j++)
#pragma unroll
            for (int i = 0; i < 4; i++) oacc[mf][j][i] = 0.f;
    float creg[4] = {0.f, 0.f, 0.f, 0.f};
    const float r_bs1 = __ldg(bs1), r_Ws2 = __ldg(Ws2), r_bs2 = __ldg(bs2), r_bc2 = __ldg(bc2);

    for (int n = 0; n < NAGENT; n++) {
        const u32 pin  = sb + ((n & 1) ? RB : RA);   // L1 input (states), L2 output, L3 input
        const u32 pmid = sb + ((n & 1) ? RA : RB);   // L1 output, L2 input, convert(n+1) dest

        // ---- L1 phase: weights ready + all prior smem writes visible ----
        cp_wait<0>();
        __syncthreads();

        // L2-prefetch next agent's DRAM-side data (no group semantics, pure warm-up):
        // states(n+1) 32KB + W1(n+1) 32KB, one 128B line per thread each.
        if (n < NAGENT - 1) {
            pf_l2((const unsigned char*)(states + ((size_t)(n + 1) * BATCH + b0) * 128)
                  + tid * 128);
            pf_l2(g_w + (size_t)(n + 1) * 81920 + tid * 128);
        }

        {
            const float* b1n = b1 + n * 128;
            if (nw < 2) {
                float C[2][6][4];
                gemm2m<6>(C, pin, sb + RW, m0, nw * 6, lane);
                __syncthreads();    // pin + RW consumed
                {   // stream W2 while epilogue runs
                    const unsigned char* src = g_w + (size_t)n * 81920 + 32768;
                    for (int i = tid * 16; i < 32768; i += 4096) cp16(sb + RW + i, src + i);
                    cp_commit();    // [W2]
                }
                if (nw == 0)
                    epi_L1<6, 0>(C, pmid, b1n, bc1, Wc2, r_bs1, r_Ws2, r_bs2, r_bc2,
                                 sG, creg, m0, lane, q);
                else
                    epi_L1<6, 6>(C, pmid, b1n, bc1, Wc2, r_bs1, r_Ws2, r_bs2, r_bc2,
                                 sG, creg, m0, lane, q);
            } else {
                float C[2][5][4];
                gemm2m<5>(C, pin, sb + RW, m0, (nw == 2) ? 12 : 17, lane);
                __syncthreads();
                {
                    const unsigned char* src = g_w + (size_t)n * 81920 + 32768;
                    for (int i = tid * 16; i < 32768; i += 4096) cp16(sb + RW + i, src + i);
                    cp_commit();    // [W2]
                }
                if (nw == 2)
                    epi_L1<5, 12>(C, pmid, b1n, bc1, Wc2, r_bs1, r_Ws2, r_bs2, r_bc2,
                                  sG, creg, m0, lane, q);
                else
                    epi_L1<5, 17>(C, pmid, b1n, bc1, Wc2, r_bs1, r_Ws2, r_bs2, r_bc2,
                                  sG, creg, m0, lane, q);
            }
        }
        cp_wait<0>();
        __syncthreads();

        // ---- L2: pmid @ W2 -> pin ----
        {
            float C[2][4][4];
            gemm2m<4>(C, pmid, sb + RW, m0, nw * 4, lane);
            __syncthreads();        // pmid + RW consumed
            {   // stream W3 + states(n+1)
                const unsigned char* src = g_w + (size_t)n * 81920 + 65536;
                for (int i = tid * 16; i < 16384; i += 4096) cp16(sb + RW + i, src + i);
                cp_commit();        // [W3]
                if (n < NAGENT - 1) {
                    const unsigned char* Sn =
                        (const unsigned char*)(states + ((size_t)(n + 1) * BATCH + b0) * 128);
                    for (int i = tid * 16; i < 32768; i += 4096) cp16(sb + RST + i, Sn + i);
                }
                cp_commit();        // [W3, S'] (S' empty at n=7; keeps group count)
            }
            const float* b2n = b2 + n * 128;
#pragma unroll
            for (int j = 0; j < 4; j++) {
                int tile = nw * 4 + j;
                int col = tile * 8 + q;
                float bx = __ldg(b2n + col), by = __ldg(b2n + col + 1);
#pragma unroll
                for (int mf = 0; mf < 2; mf++) {
                    int row0 = m0 + mf * 16 + (lane >> 2), row8 = row0 + 8;
                    u32 h0 = pack_h(fmaxf(C[mf][j][0] + bx, 0.f), fmaxf(C[mf][j][1] + by, 0.f));
                    u32 h2 = pack_h(fmaxf(C[mf][j][2] + bx, 0.f), fmaxf(C[mf][j][3] + by, 0.f));
                    u32 sw0 = ((u32)(((tile ^ row0) & 7) | (tile & 8))) << 4;
                    u32 sw8 = ((u32)(((tile ^ row8) & 7) | (tile & 8))) << 4;
                    asm volatile("st.shared.b32 [%0], %1;"
                        :: "r"(pin + (u32)row0 * 256 + sw0 + (u32)(q * 2)), "r"(h0));
                    asm volatile("st.shared.b32 [%0], %1;"
                        :: "r"(pin + (u32)row8 * 256 + sw8 + (u32)(q * 2)), "r"(h2));
                }
            }
        }
        cp_wait<1>();               // W3 ready (S' may be outstanding)
        __syncthreads();

        // ---- L3: pin @ W3 -> oacc ; convert(n+1) -> pmid hides under the gemm ----
        {
            float C[2][2][4];
            gemm2m<2>(C, pin, sb + RW, m0, nw * 2, lane);
            if (n < NAGENT - 1) {
                cp_wait<0>();               // own states(n+1) chunks done
                convert_own(sb, pmid, tid); // pmid free (L2 consumed it)
            }
            const float* b3n = b3 + n * 64;
#pragma unroll
            for (int mf = 0; mf < 2; mf++) {
                int row0 = m0 + mf * 16 + (lane >> 2), row8 = row0 + 8;
                float g0 = sG[row0], g8 = sG[row8];
#pragma unroll
                for (int j = 0; j < 2; j++) {
                    int col = (nw * 2 + j) * 8 + q;
                    float bx = __ldg(b3n + col), by = __ldg(b3n + col + 1);
                    oacc[mf][j][0] = fmaf(g0, C[mf][j][0] + bx, oacc[mf][j][0]);
                    oacc[mf][j][1] = fmaf(g0, C[mf][j][1] + by, oacc[mf][j][1]);
                    oacc[mf][j][2] = fmaf(g8, C[mf][j][2] + bx, oacc[mf][j][2]);
                    oacc[mf][j][3] = fmaf(g8, C[mf][j][3] + by, oacc[mf][j][3]);
                }
            }
            __syncthreads();        // pin + RW consumed; convert visible
            if (n < NAGENT - 1) {   // stream W1(n+1) (aux rows persist)
                const unsigned char* src = g_w + (size_t)(n + 1) * 81920;
                for (int i = tid * 16; i < 32768; i += 4096) cp16(sb + RW + i, src + i);
                cp_commit();        // [W1']
            }
        }
    }

    // ---- final: csum exchange + output ----
    if ((nw == 2 || nw == 3) && (lane & 3) == 0) {
        int slot = nw - 2;
#pragma unroll
        for (int i = 0; i < 4; i++) {
            int row = m0 + (i >> 1) * 16 + (i & 1) * 8 + (lane >> 2);
            sRd[row * 2 + slot] = creg[i];
        }
    }
    __syncthreads();
#pragma unroll
    for (int mf = 0; mf < 2; mf++) {
#pragma unroll
        for (int h = 0; h < 2; h++) {
            int row = m0 + mf * 16 + h * 8 + (lane >> 2);
            float cs = (sRd[row * 2] + sRd[row * 2 + 1]) * 0.125f;
#pragma unroll
            for (int j = 0; j < 2; j++) {
                int col = (nw * 2 + j) * 8 + q;
                float2 v;
                v.x = fmaf(oacc[mf][j][2 * h + 0], 0.125f, cs);
                v.y = fmaf(oacc[mf][j][2 * h + 1], 0.125f, cs);
                *(float2*)(out + (size_t)(b0 + row) * 64 + col) = v;
            }
        }
    }
}

extern "C" void kernel_launch(void* const* d_in, const int* in_sizes, int n_in,
                              void* d_out, int out_size)
{
    const float* states = (const float*)d_in[0];
    const float* W1  = (const float*)d_in[1];
    const float* b1  = (const float*)d_in[2];
    const float* W2  = (const float*)d_in[3];
    const float* b2  = (const float*)d_in[4];
    const float* W3  = (const float*)d_in[5];
    const float* b3  = (const float*)d_in[6];
    // d_in[7..12]: Wq1,bq1,Wq2,bq2,Wk,bk — dead (softmax rows sum to 1)
    const float* Ws1 = (const float*)d_in[13];
    const float* bs1 = (const float*)d_in[14];
    const float* Ws2 = (const float*)d_in[15];
    const float* bs2 = (const float*)d_in[16];
    const float* Wc1 = (const float*)d_in[17];
    const float* bc1 = (const float*)d_in[18];
    const float* Wc2 = (const float*)d_in[19];
    const float* bc2 = (const float*)d_in[20];
    float* out = (float*)d_out;

    prep_kernel<<<(81920 + 1536 + 255) / 256, 256>>>(W1, W2, W3, Wc1, Ws1);

    cudaFuncSetAttribute(qatten_mma,
                         cudaFuncAttributeMaxDynamicSharedMemorySize, SMEM_TOTAL);
    qatten_mma<<<BATCH / BM, 256, SMEM_TOTAL>>>(
        states, b1, b2, b3, bs1, Ws2, bs2, bc1, Wc2, bc2, out);
}

// round 14
// speedup vs baseline: 1.0777x; 1.0229x over previous
#include <cuda_runtime.h>
#include <cuda_fp16.h>
#include <cstdint>

typedef unsigned u32;

#define NAGENT 8
#define BATCH  32768
#define BM     64

// ---- scratch: pre-swizzled fp16 weights ----
// per agent: L1 (128 rows) off 0, L2 off 32768, L3 (64 rows) off 65536; stride 81920
__device__ __align__(16) unsigned char g_w[8 * 81920];
__device__ __align__(16) unsigned char g_ax[48 * 256];   // aux: Wc1^T rows 0-31, Ws1 row 32, pad

// ---- smem byte offsets (per CTA, ~109 KB -> 2 CTAs/SM) ----
#define RA    0          // plane P0: 64 rows x 256B fp16
#define RB    16384      // plane P1
#define RST   32768      // f32 states staging (64 x 512B = 32KB)
#define RW    65536      // weights, 176 rows x 256B = 45056 (aux rows 128-175 persist)
#define SGOFF 110592     // gate per row (64 f32)
#define SREDO 110848     // csum partials (64 rows x 2 slots)
#define SMEM_TOTAL 111616

// ======================= helpers =======================
__device__ __forceinline__ u32 smem_u32(const void* p) {
    u32 a; asm("{ .reg .u64 t; cvta.to.shared.u64 t, %1; cvt.u32.u64 %0, t; }" : "=r"(a) : "l"(p));
    return a;
}
__device__ __forceinline__ void cp16(u32 dst, const void* src) {
    asm volatile("cp.async.cg.shared.global [%0], [%1], 16;" :: "r"(dst), "l"(src));
}
__device__ __forceinline__ void cp_commit() { asm volatile("cp.async.commit_group;"); }
template<int N> __device__ __forceinline__ void cp_wait() {
    asm volatile("cp.async.wait_group %0;" :: "n"(N) : "memory");
}
__device__ __forceinline__ u32 pack_h(float x, float y) {
    __half2 h = __floats2half2_rn(x, y);
    return *reinterpret_cast<u32*>(&h);
}
// plane byte offset: row n, half-col k; 256B rows, XOR swizzle on 16B chunks
__device__ __forceinline__ u32 plane_off(int n, int k) {
    int c = k >> 3;
    u32 sw = (u32)(((c ^ n) & 7) | (c & 8));
    return (u32)(n * 256) + (sw << 4) + (u32)((k & 7) * 2);
}
__device__ __forceinline__ void ldm4(u32* a, u32 addr) {
    asm volatile("ldmatrix.sync.aligned.m8n8.x4.shared.b16 {%0,%1,%2,%3}, [%4];"
        : "=r"(a[0]), "=r"(a[1]), "=r"(a[2]), "=r"(a[3]) : "r"(addr));
}
__device__ __forceinline__ void ldm2(u32* b, u32 addr) {
    asm volatile("ldmatrix.sync.aligned.m8n8.x2.shared.b16 {%0,%1}, [%2];"
        : "=r"(b[0]), "=r"(b[1]) : "r"(addr));
}
__device__ __forceinline__ void mma_h(float* d, const u32* a, const u32* b) {
    asm volatile("mma.sync.aligned.m16n8k16.row.col.f32.f16.f16.f32 "
        "{%0,%1,%2,%3}, {%4,%5,%6,%7}, {%8,%9}, {%0,%1,%2,%3};"
        : "+f"(d[0]), "+f"(d[1]), "+f"(d[2]), "+f"(d[3])
        : "r"(a[0]), "r"(a[1]), "r"(a[2]), "r"(a[3]), "r"(b[0]), "r"(b[1]));
}

// convert own-copied f32 chunks (RST) -> fp16 plane. Each thread touches exactly
// the bytes it cp.async'd (same tid*16 + 4096j mapping) => only own-group wait needed.
__device__ __forceinline__ void convert_own(u32 sb, u32 dst, int tid) {
#pragma unroll
    for (int j = 0; j < 8; j++) {
        int o = tid * 16 + 4096 * j;
        int m = o >> 9, c4 = (o & 511) >> 4;
        float4 v;
        asm volatile("ld.shared.v4.f32 {%0,%1,%2,%3}, [%4];"
            : "=f"(v.x), "=f"(v.y), "=f"(v.z), "=f"(v.w) : "r"(sb + RST + o));
        u32 h0 = pack_h(v.x, v.y);
        u32 h1 = pack_h(v.z, v.w);
        asm volatile("st.shared.v2.b32 [%0], {%1,%2};"
            :: "r"(dst + plane_off(m, c4 * 4)), "r"(h0), "r"(h1));
    }
}

// ============ warp GEMM: 32 M-rows (MF=2), NF n8-tiles, paired x4 B loads ============
template<int NF>
__device__ __forceinline__ void gemm2m(float C[2][NF][4], u32 ah, u32 bw,
                                       int m0, int tbase, int lane)
{
#pragma unroll
    for (int mf = 0; mf < 2; mf++)
#pragma unroll
        for (int j = 0; j < NF; j++)
#pragma unroll
            for (int i = 0; i < 4; i++) C[mf][j][i] = 0.f;

    const int rA = m0 + (lane & 7) + ((lane >> 3) & 1) * 8;
    const int gA = lane >> 4;
    const u32 oA = (u32)rA * 256;
    const int rBl = lane & 7;
    const int gB = (lane >> 3) & 1;
    const int tsel = (lane >> 4) & 1;

#pragma unroll
    for (int t = 0; t < 8; t++) {
        const int cA = 2 * t + gA;
        const u32 swA = ((u32)(((cA ^ rA) & 7) | (cA & 8))) << 4;
        u32 A0[4], A1[4];
        ldm4(A0, ah + oA + swA);            // rows m0..m0+15
        ldm4(A1, ah + oA + 4096 + swA);     // rows m0+16..m0+31

        const int cB = 2 * t + gB;
#pragma unroll
        for (int jp = 0; jp < NF / 2; jp++) {
            int tile = tbase + 2 * jp + tsel;
            int rB = tile * 8 + rBl;
            u32 swB = ((u32)(((cB ^ rB) & 7) | (cB & 8))) << 4;
            u32 B4[4];
            ldm4(B4, bw + (u32)rB * 256 + swB);
            mma_h(C[0][2 * jp],     A0, B4);
            mma_h(C[0][2 * jp + 1], A0, B4 + 2);
            mma_h(C[1][2 * jp],     A1, B4);
            mma_h(C[1][2 * jp + 1], A1, B4 + 2);
        }
        if (NF & 1) {
            int tile = tbase + NF - 1;
            int rB = tile * 8 + rBl;
            u32 swB = ((u32)(((cB ^ rB) & 7) | (cB & 8))) << 4;
            u32 B2[2];
            ldm2(B2, bw + (u32)rB * 256 + swB);
            mma_h(C[0][NF - 1], A0, B2);
            mma_h(C[1][NF - 1], A1, B2);
        }
    }
}

// ======================= L1 epilogue (activation stores to dst + aux) =======================
template<int NF, int TBASE>
__device__ __forceinline__ void epi_L1(float C[2][NF][4], u32 dst,
    const float* __restrict__ b1n, const float* __restrict__ bc1,
    const float* __restrict__ Wc2,
    float r_bs1, float r_Ws2, float r_bs2, float r_bc2,
    float* sG, float creg[4], int m0, int lane, int q)
{
    float cp[4] = {0.f, 0.f, 0.f, 0.f};
#pragma unroll
    for (int j = 0; j < NF; j++) {
        const int tile = TBASE + j;
        if (tile < 16) {
            int col = tile * 8 + q;
            float bx = __ldg(b1n + col), by = __ldg(b1n + col + 1);
#pragma unroll
            for (int mf = 0; mf < 2; mf++) {
                int row0 = m0 + mf * 16 + (lane >> 2), row8 = row0 + 8;
                u32 h0 = pack_h(fmaxf(C[mf][j][0] + bx, 0.f), fmaxf(C[mf][j][1] + by, 0.f));
                u32 h2 = pack_h(fmaxf(C[mf][j][2] + bx, 0.f), fmaxf(C[mf][j][3] + by, 0.f));
                u32 sw0 = ((u32)(((tile ^ row0) & 7) | (tile & 8))) << 4;
                u32 sw8 = ((u32)(((tile ^ row8) & 7) | (tile & 8))) << 4;
                asm volatile("st.shared.b32 [%0], %1;"
                    :: "r"(dst + (u32)row0 * 256 + sw0 + (u32)(q * 2)), "r"(h0));
                asm volatile("st.shared.b32 [%0], %1;"
                    :: "r"(dst + (u32)row8 * 256 + sw8 + (u32)(q * 2)), "r"(h2));
            }
        } else if (tile < 20) {     // constraint cols: e in [0,32)
            int e = (tile - 16) * 8 + q;
            float bb0 = __ldg(bc1 + e),  bb1 = __ldg(bc1 + e + 1);
            float w0  = __ldg(Wc2 + e),  w1  = __ldg(Wc2 + e + 1);
#pragma unroll
            for (int mf = 0; mf < 2; mf++) {
                cp[mf * 2 + 0] = fmaf(fmaxf(C[mf][j][0] + bb0, 0.f), w0,
                                 fmaf(fmaxf(C[mf][j][1] + bb1, 0.f), w1, cp[mf * 2 + 0]));
                cp[mf * 2 + 1] = fmaf(fmaxf(C[mf][j][2] + bb0, 0.f), w0,
                                 fmaf(fmaxf(C[mf][j][3] + bb1, 0.f), w1, cp[mf * 2 + 1]));
            }
        } else if (tile == 20) {    // gate col (e==32) at q==0
            if (q == 0) {
#pragma unroll
                for (int mf = 0; mf < 2; mf++) {
                    int row0 = m0 + mf * 16 + (lane >> 2), row8 = row0 + 8;
                    float s0 = fmaf(fmaxf(C[mf][j][0] + r_bs1, 0.f), r_Ws2, r_bs2);
                    float s8 = fmaf(fmaxf(C[mf][j][2] + r_bs1, 0.f), r_Ws2, r_bs2);
                    sG[row0] = 1.f / (1.f + __expf(-s0));
                    sG[row8] = 1.f / (1.f + __expf(-s8));
                }
            }
        }
        // tile 21: zero padding, skip
    }
    if (TBASE >= 12) {              // constraint-carrying warps (nw 2,3)
#pragma unroll
        for (int i = 0; i < 4; i++) {
            cp[i] += __shfl_xor_sync(0xffffffffu, cp[i], 1);
            cp[i] += __shfl_xor_sync(0xffffffffu, cp[i], 2);
        }
        if ((lane & 3) == 0) {
            float add = (TBASE == 12) ? r_bc2 : 0.f;
#pragma unroll
            for (int i = 0; i < 4; i++) creg[i] += cp[i] + add;
        }
    }
}

// ======================= prep kernel: fp32 weights -> swizzled fp16 =======================
extern "C" __global__ void __launch_bounds__(256)
prep_kernel(const float* __restrict__ W1, const float* __restrict__ W2,
            const float* __restrict__ W3, const float* __restrict__ Wc1,
            const float* __restrict__ Ws1)
{
    int idx = blockIdx.x * 256 + threadIdx.x;
    if (idx < 81920) {
        int agent = idx / 10240;
        int rem = idx % 10240;
        int row = rem >> 5;
        int k = (rem & 31) * 4;
        const float* src; int n, N; u32 loff;
        if (row < 128)      { src = W1 + agent * 16384; n = row;       N = 128; loff = 0; }
        else if (row < 256) { src = W2 + agent * 16384; n = row - 128; N = 128; loff = 32768; }
        else                { src = W3 + agent * 8192;  n = row - 256; N = 64;  loff = 65536; }
        u32 h0 = pack_h(src[(k + 0) * N + n], src[(k + 1) * N + n]);
        u32 h1 = pack_h(src[(k + 2) * N + n], src[(k + 3) * N + n]);
        *(uint2*)(g_w + (u32)agent * 81920 + loff + plane_off(n, k)) = make_uint2(h0, h1);
    } else if (idx < 81920 + 1536) {
        int rem = idx - 81920;
        int row = rem >> 5;
        int k = (rem & 31) * 4;
        float w[4];
#pragma unroll
        for (int i = 0; i < 4; i++) {
            int kk = k + i;
            w[i] = (row < 32) ? __ldg(Wc1 + kk * 32 + row) : (row == 32 ? __ldg(Ws1 + kk) : 0.f);
        }
        *(uint2*)(g_ax + plane_off(row, k)) =
            make_uint2(pack_h(w[0], w[1]), pack_h(w[2], w[3]));
    }
}

// ======================= main kernel =======================
extern "C" __global__ void __launch_bounds__(256, 2)
qatten_mma(const float* __restrict__ states,
           const float* __restrict__ b1, const float* __restrict__ b2,
           const float* __restrict__ b3,
           const float* __restrict__ bs1, const float* __restrict__ Ws2,
           const float* __restrict__ bs2,
           const float* __restrict__ bc1, const float* __restrict__ Wc2,
           const float* __restrict__ bc2,
           float* __restrict__ out)
{
    extern __shared__ char smem[];
    const u32 sb = smem_u32(smem);
    const int tid = threadIdx.x;
    const int wid = tid >> 5, lane = tid & 31;
    const int b0 = blockIdx.x * BM;

    const int mq = wid & 1, nw = wid >> 1;   // 2 M-slices x 4 N-slices
    const int m0 = mq * 32;
    const int q = (lane & 3) * 2;

    float* sG  = (float*)(smem + SGOFF);
    float* sRd = (float*)(smem + SREDO);

    // ---- prologue: stage states(0) -> RST; W1(0)+aux -> RW; convert(0) -> P0 ----
    {
        const unsigned char* S0 = (const unsigned char*)(states + (size_t)b0 * 128);
        for (int i = tid * 16; i < 32768; i += 4096) cp16(sb + RST + i, S0 + i);
        cp_commit();                                        // [S]
        for (int i = tid * 16; i < 32768; i += 4096) cp16(sb + RW + i, g_w + i);
        for (int i = tid * 16; i < 12288; i += 4096) cp16(sb + RW + 32768 + i, g_ax + i);
        cp_commit();                                        // [S, W1]
        cp_wait<1>();                // own states chunks done (W1 outstanding)
        convert_own(sb, sb + RA, tid);   // states(0) -> P0
    }

    float oacc[2][2][4];
#pragma unroll
    for (int mf = 0; mf < 2; mf++)
#pragma unroll
        for (int j = 0; j < 2; j++)
#pragma unroll
            for (int i = 0; i < 4; i++) oacc[mf][j][i] = 0.f;
    float creg[4] = {0.f, 0.f, 0.f, 0.f};
    const float r_bs1 = __ldg(bs1), r_Ws2 = __ldg(Ws2), r_bs2 = __ldg(bs2), r_bc2 = __ldg(bc2);

    for (int n = 0; n < NAGENT; n++) {
        const u32 pin  = sb + ((n & 1) ? RB : RA);   // L1 input (states), L2 output, L3 input
        const u32 pmid = sb + ((n & 1) ? RA : RB);   // L1 output, L2 input, convert(n+1) dest

        // ---- L1 phase: weights ready + all prior smem writes visible ----
        cp_wait<0>();
        __syncthreads();
        {
            const float* b1n = b1 + n * 128;
            if (nw < 2) {
                float C[2][6][4];
                gemm2m<6>(C, pin, sb + RW, m0, nw * 6, lane);
                __syncthreads();    // pin + RW consumed
                {   // stream W2 while epilogue runs
                    const unsigned char* src = g_w + (size_t)n * 81920 + 32768;
                    for (int i = tid * 16; i < 32768; i += 4096) cp16(sb + RW + i, src + i);
                    cp_commit();    // [W2]
                }
                if (nw == 0)
                    epi_L1<6, 0>(C, pmid, b1n, bc1, Wc2, r_bs1, r_Ws2, r_bs2, r_bc2,
                                 sG, creg, m0, lane, q);
                else
                    epi_L1<6, 6>(C, pmid, b1n, bc1, Wc2, r_bs1, r_Ws2, r_bs2, r_bc2,
                                 sG, creg, m0, lane, q);
            } else {
                float C[2][5][4];
                gemm2m<5>(C, pin, sb + RW, m0, (nw == 2) ? 12 : 17, lane);
                __syncthreads();
                {
                    const unsigned char* src = g_w + (size_t)n * 81920 + 32768;
                    for (int i = tid * 16; i < 32768; i += 4096) cp16(sb + RW + i, src + i);
                    cp_commit();    // [W2]
                }
                if (nw == 2)
                    epi_L1<5, 12>(C, pmid, b1n, bc1, Wc2, r_bs1, r_Ws2, r_bs2, r_bc2,
                                  sG, creg, m0, lane, q);
                else
                    epi_L1<5, 17>(C, pmid, b1n, bc1, Wc2, r_bs1, r_Ws2, r_bs2, r_bc2,
                                  sG, creg, m0, lane, q);
            }
        }
        cp_wait<0>();
        __syncthreads();

        // ---- L2: pmid @ W2 -> pin ----
        {
            float C[2][4][4];
            gemm2m<4>(C, pmid, sb + RW, m0, nw * 4, lane);
            __syncthreads();        // pmid + RW consumed (ALL of W2 dead now)
            {   // stream W3 -> RW+16K (rows 64..127 slot) AND W1'(rows 0..63) -> RW+0
                const unsigned char* w3s = g_w + (size_t)n * 81920 + 65536;
                for (int i = tid * 16; i < 16384; i += 4096) cp16(sb + RW + 16384 + i, w3s + i);
                if (n < NAGENT - 1) {
                    const unsigned char* w1a = g_w + (size_t)(n + 1) * 81920;
                    for (int i = tid * 16; i < 16384; i += 4096) cp16(sb + RW + i, w1a + i);
                }
                cp_commit();        // [Wx = W3 + W1'a]
                if (n < NAGENT - 1) {
                    const unsigned char* Sn =
                        (const unsigned char*)(states + ((size_t)(n + 1) * BATCH + b0) * 128);
                    for (int i = tid * 16; i < 32768; i += 4096) cp16(sb + RST + i, Sn + i);
                }
                cp_commit();        // [Wx, S'] (S' empty at n=7; keeps group count)
            }
            const float* b2n = b2 + n * 128;
#pragma unroll
            for (int j = 0; j < 4; j++) {
                int tile = nw * 4 + j;
                int col = tile * 8 + q;
                float bx = __ldg(b2n + col), by = __ldg(b2n + col + 1);
#pragma unroll
                for (int mf = 0; mf < 2; mf++) {
                    int row0 = m0 + mf * 16 + (lane >> 2), row8 = row0 + 8;
                    u32 h0 = pack_h(fmaxf(C[mf][j][0] + bx, 0.f), fmaxf(C[mf][j][1] + by, 0.f));
                    u32 h2 = pack_h(fmaxf(C[mf][j][2] + bx, 0.f), fmaxf(C[mf][j][3] + by, 0.f));
                    u32 sw0 = ((u32)(((tile ^ row0) & 7) | (tile & 8))) << 4;
                    u32 sw8 = ((u32)(((tile ^ row8) & 7) | (tile & 8))) << 4;
                    asm volatile("st.shared.b32 [%0], %1;"
                        :: "r"(pin + (u32)row0 * 256 + sw0 + (u32)(q * 2)), "r"(h0));
                    asm volatile("st.shared.b32 [%0], %1;"
                        :: "r"(pin + (u32)row8 * 256 + sw8 + (u32)(q * 2)), "r"(h2));
                }
            }
        }
        cp_wait<1>();               // Wx (W3 + W1'a) ready; S' may be outstanding
        __syncthreads();

        // ---- L3: pin @ W3(@RW+16K) -> oacc ; convert(n+1) -> pmid hides under the gemm ----
        {
            float C[2][2][4];
            gemm2m<2>(C, pin, sb + RW + 16384, m0, nw * 2, lane);
            if (n < NAGENT - 1) {
                cp_wait<0>();               // own states(n+1) chunks done
                convert_own(sb, pmid, tid); // pmid free (L2 consumed it)
            }
            const float* b3n = b3 + n * 64;
#pragma unroll
            for (int mf = 0; mf < 2; mf++) {
                int row0 = m0 + mf * 16 + (lane >> 2), row8 = row0 + 8;
                float g0 = sG[row0], g8 = sG[row8];
#pragma unroll
                for (int j = 0; j < 2; j++) {
                    int col = (nw * 2 + j) * 8 + q;
                    float bx = __ldg(b3n + col), by = __ldg(b3n + col + 1);
                    oacc[mf][j][0] = fmaf(g0, C[mf][j][0] + bx, oacc[mf][j][0]);
                    oacc[mf][j][1] = fmaf(g0, C[mf][j][1] + by, oacc[mf][j][1]);
                    oacc[mf][j][2] = fmaf(g8, C[mf][j][2] + bx, oacc[mf][j][2]);
                    oacc[mf][j][3] = fmaf(g8, C[mf][j][3] + by, oacc[mf][j][3]);
                }
            }
            __syncthreads();        // pin + W3 region consumed; convert visible
            if (n < NAGENT - 1) {   // stream only W1'(rows 64..127) -> RW+16K
                const unsigned char* w1b = g_w + (size_t)(n + 1) * 81920 + 16384;
                for (int i = tid * 16; i < 16384; i += 4096) cp16(sb + RW + 16384 + i, w1b + i);
                cp_commit();        // [W1'b]
            }
        }
    }

    // ---- final: csum exchange + output ----
    if ((nw == 2 || nw == 3) && (lane & 3) == 0) {
        int slot = nw - 2;
#pragma unroll
        for (int i = 0; i < 4; i++) {
            int row = m0 + (i >> 1) * 16 + (i & 1) * 8 + (lane >> 2);
            sRd[row * 2 + slot] = creg[i];
        }
    }
    __syncthreads();
#pragma unroll
    for (int mf = 0; mf < 2; mf++) {
#pragma unroll
        for (int h = 0; h < 2; h++) {
            int row = m0 + mf * 16 + h * 8 + (lane >> 2);
            float cs = (sRd[row * 2] + sRd[row * 2 + 1]) * 0.125f;
#pragma unroll
            for (int j = 0; j < 2; j++) {
                int col = (nw * 2 + j) * 8 + q;
                float2 v;
                v.x = fmaf(oacc[mf][j][2 * h + 0], 0.125f, cs);
                v.y = fmaf(oacc[mf][j][2 * h + 1], 0.125f, cs);
                *(float2*)(out + (size_t)(b0 + row) * 64 + col) = v;
            }
        }
    }
}

extern "C" void kernel_launch(void* const* d_in, const int* in_sizes, int n_in,
                              void* d_out, int out_size)
{
    const float* states = (const float*)d_in[0];
    const float* W1  = (const float*)d_in[1];
    const float* b1  = (const float*)d_in[2];
    const float* W2  = (const float*)d_in[3];
    const float* b2  = (const float*)d_in[4];
    const float* W3  = (const float*)d_in[5];
    const float* b3  = (const float*)d_in[6];
    // d_in[7..12]: Wq1,bq1,Wq2,bq2,Wk,bk — dead (softmax rows sum to 1)
    const float* Ws1 = (const float*)d_in[13];
    const float* bs1 = (const float*)d_in[14];
    const float* Ws2 = (const float*)d_in[15];
    const float* bs2 = (const float*)d_in[16];
    const float* Wc1 = (const float*)d_in[17];
    const float* bc1 = (const float*)d_in[18];
    const float* Wc2 = (const float*)d_in[19];
    const float* bc2 = (const float*)d_in[20];
    float* out = (float*)d_out;

    prep_kernel<<<(81920 + 1536 + 255) / 256, 256>>>(W1, W2, W3, Wc1, Ws1);

    cudaFuncSetAttribute(qatten_mma,
                         cudaFuncAttributeMaxDynamicSharedMemorySize, SMEM_TOTAL);
    qatten_mma<<<BATCH / BM, 256, SMEM_TOTAL>>>(
        states, b1, b2, b3, bs1, Ws2, bs2, bc1, Wc2, bc2, out);
}

// round 15
// speedup vs baseline: 1.0864x; 1.0081x over previous
#include <cuda_runtime.h>
#include <cuda_fp16.h>
#include <cstdint>

typedef unsigned u32;

#define NAGENT 8
#define BATCH  32768
#define BM     64

// ---- scratch: pre-swizzled fp16 weights ----
// per agent: L1 (128 rows) off 0, L2 off 32768, L3 (64 rows) off 65536; stride 81920
__device__ __align__(16) unsigned char g_w[8 * 81920];
__device__ __align__(16) unsigned char g_ax[48 * 256];   // aux: Wc1^T rows 0-31, Ws1 row 32, pad

// ---- smem byte offsets (per CTA, ~78.6 KB -> 2 CTAs/SM) ----
#define RA    0          // plane P0: 64 rows x 256B fp16
#define RB    16384      // plane P1
#define RW    32768      // weights, 176 rows x 256B = 45056 (aux rows 128-175 persist)
#define SGOFF 77824      // gate per row (64 f32)
#define SREDO 78080      // csum per row (64 f32)
#define SMEM_TOTAL 78592

// ======================= helpers =======================
__device__ __forceinline__ u32 smem_u32(const void* p) {
    u32 a; asm("{ .reg .u64 t; cvta.to.shared.u64 t, %1; cvt.u32.u64 %0, t; }" : "=r"(a) : "l"(p));
    return a;
}
__device__ __forceinline__ void cp16(u32 dst, const void* src) {
    asm volatile("cp.async.cg.shared.global [%0], [%1], 16;" :: "r"(dst), "l"(src));
}
__device__ __forceinline__ void cp_commit() { asm volatile("cp.async.commit_group;"); }
template<int N> __device__ __forceinline__ void cp_wait() {
    asm volatile("cp.async.wait_group %0;" :: "n"(N) : "memory");
}
__device__ __forceinline__ u32 pack_h(float x, float y) {
    __half2 h = __floats2half2_rn(x, y);
    return *reinterpret_cast<u32*>(&h);
}
// plane byte offset: row n, half-col k; 256B rows, XOR swizzle on 16B chunks
__device__ __forceinline__ u32 plane_off(int n, int k) {
    int c = k >> 3;
    u32 sw = (u32)(((c ^ n) & 7) | (c & 8));
    return (u32)(n * 256) + (sw << 4) + (u32)((k & 7) * 2);
}
__device__ __forceinline__ void ldm4(u32* a, u32 addr) {
    asm volatile("ldmatrix.sync.aligned.m8n8.x4.shared.b16 {%0,%1,%2,%3}, [%4];"
        : "=r"(a[0]), "=r"(a[1]), "=r"(a[2]), "=r"(a[3]) : "r"(addr));
}
__device__ __forceinline__ void ldm2(u32* b, u32 addr) {
    asm volatile("ldmatrix.sync.aligned.m8n8.x2.shared.b16 {%0,%1}, [%2];"
        : "=r"(b[0]), "=r"(b[1]) : "r"(addr));
}
__device__ __forceinline__ void mma_h(float* d, const u32* a, const u32* b) {
    asm volatile("mma.sync.aligned.m16n8k16.row.col.f32.f16.f16.f32 "
        "{%0,%1,%2,%3}, {%4,%5,%6,%7}, {%8,%9}, {%0,%1,%2,%3};"
        : "+f"(d[0]), "+f"(d[1]), "+f"(d[2]), "+f"(d[3])
        : "r"(a[0]), "r"(a[1]), "r"(a[2]), "r"(a[3]), "r"(b[0]), "r"(b[1]));
}
__device__ __forceinline__ float4 ldg_v4(const void* p) {
    float4 v;
    asm("ld.global.v4.f32 {%0,%1,%2,%3}, [%4];"
        : "=f"(v.x), "=f"(v.y), "=f"(v.z), "=f"(v.w) : "l"(p));
    return v;
}

// convert 8 register-resident float4 chunks -> fp16 plane (thread's own chunks:
// chunk j covers plane bytes o = tid*16 + 4096*j of the 64x512B f32 tile).
__device__ __forceinline__ void convert_regs(const float4* s, u32 dst, int tid) {
#pragma unroll
    for (int j = 0; j < 8; j++) {
        int o = tid * 16 + 4096 * j;
        int m = o >> 9, c4 = (o & 511) >> 4;
        u32 h0 = pack_h(s[j].x, s[j].y);
        u32 h1 = pack_h(s[j].z, s[j].w);
        asm volatile("st.shared.v2.b32 [%0], {%1,%2};"
            :: "r"(dst + plane_off(m, c4 * 4)), "r"(h0), "r"(h1));
    }
}
__device__ __forceinline__ void load_states_regs(float4* s, const float* base, int tid) {
#pragma unroll
    for (int j = 0; j < 8; j++)
        s[j] = ldg_v4((const unsigned char*)base + tid * 16 + 4096 * j);
}

// ============ warp GEMM: 32 M-rows (MF=2), NF n8-tiles, paired x4 B loads ============
template<int NF>
__device__ __forceinline__ void gemm2m(float C[2][NF][4], u32 ah, u32 bw,
                                       int m0, int tbase, int lane)
{
#pragma unroll
    for (int mf = 0; mf < 2; mf++)
#pragma unroll
        for (int j = 0; j < NF; j++)
#pragma unroll
            for (int i = 0; i < 4; i++) C[mf][j][i] = 0.f;

    const int rA = m0 + (lane & 7) + ((lane >> 3) & 1) * 8;
    const int gA = lane >> 4;
    const u32 oA = (u32)rA * 256;
    const int rBl = lane & 7;
    const int gB = (lane >> 3) & 1;
    const int tsel = (lane >> 4) & 1;

#pragma unroll
    for (int t = 0; t < 8; t++) {
        const int cA = 2 * t + gA;
        const u32 swA = ((u32)(((cA ^ rA) & 7) | (cA & 8))) << 4;
        u32 A0[4], A1[4];
        ldm4(A0, ah + oA + swA);            // rows m0..m0+15
        ldm4(A1, ah + oA + 4096 + swA);     // rows m0+16..m0+31

        const int cB = 2 * t + gB;
#pragma unroll
        for (int jp = 0; jp < NF / 2; jp++) {
            int tile = tbase + 2 * jp + tsel;
            int rB = tile * 8 + rBl;
            u32 swB = ((u32)(((cB ^ rB) & 7) | (cB & 8))) << 4;
            u32 B4[4];
            ldm4(B4, bw + (u32)rB * 256 + swB);
            mma_h(C[0][2 * jp],     A0, B4);
            mma_h(C[0][2 * jp + 1], A0, B4 + 2);
            mma_h(C[1][2 * jp],     A1, B4);
            mma_h(C[1][2 * jp + 1], A1, B4 + 2);
        }
        if (NF & 1) {
            int tile = tbase + NF - 1;
            int rB = tile * 8 + rBl;
            u32 swB = ((u32)(((cB ^ rB) & 7) | (cB & 8))) << 4;
            u32 B2[2];
            ldm2(B2, bw + (u32)rB * 256 + swB);
            mma_h(C[0][NF - 1], A0, B2);
            mma_h(C[1][NF - 1], A1, B2);
        }
    }
}

// ======================= L1 epilogue (activation stores to dst + aux) =======================
// Tiles 0..15 -> RB stores; 16..19 constraint; 20 gate. (tile 21 eliminated.)
template<int NF, int TBASE>
__device__ __forceinline__ void epi_L1(float C[2][NF][4], u32 dst,
    const float* __restrict__ b1n, const float* __restrict__ bc1,
    const float* __restrict__ Wc2,
    float r_bs1, float r_Ws2, float r_bs2, float r_bc2,
    float* sG, float creg[4], int m0, int lane, int q)
{
    float cp[4] = {0.f, 0.f, 0.f, 0.f};
#pragma unroll
    for (int j = 0; j < NF; j++) {
        const int tile = TBASE + j;
        if (tile < 16) {
            int col = tile * 8 + q;
            float bx = __ldg(b1n + col), by = __ldg(b1n + col + 1);
#pragma unroll
            for (int mf = 0; mf < 2; mf++) {
                int row0 = m0 + mf * 16 + (lane >> 2), row8 = row0 + 8;
                u32 h0 = pack_h(fmaxf(C[mf][j][0] + bx, 0.f), fmaxf(C[mf][j][1] + by, 0.f));
                u32 h2 = pack_h(fmaxf(C[mf][j][2] + bx, 0.f), fmaxf(C[mf][j][3] + by, 0.f));
                u32 sw0 = ((u32)(((tile ^ row0) & 7) | (tile & 8))) << 4;
                u32 sw8 = ((u32)(((tile ^ row8) & 7) | (tile & 8))) << 4;
                asm volatile("st.shared.b32 [%0], %1;"
                    :: "r"(dst + (u32)row0 * 256 + sw0 + (u32)(q * 2)), "r"(h0));
                asm volatile("st.shared.b32 [%0], %1;"
                    :: "r"(dst + (u32)row8 * 256 + sw8 + (u32)(q * 2)), "r"(h2));
            }
        } else if (tile < 20) {     // constraint cols: e in [0,32)
            int e = (tile - 16) * 8 + q;
            float bb0 = __ldg(bc1 + e),  bb1 = __ldg(bc1 + e + 1);
            float w0  = __ldg(Wc2 + e),  w1  = __ldg(Wc2 + e + 1);
#pragma unroll
            for (int mf = 0; mf < 2; mf++) {
                cp[mf * 2 + 0] = fmaf(fmaxf(C[mf][j][0] + bb0, 0.f), w0,
                                 fmaf(fmaxf(C[mf][j][1] + bb1, 0.f), w1, cp[mf * 2 + 0]));
                cp[mf * 2 + 1] = fmaf(fmaxf(C[mf][j][2] + bb0, 0.f), w0,
                                 fmaf(fmaxf(C[mf][j][3] + bb1, 0.f), w1, cp[mf * 2 + 1]));
            }
        } else {                    // tile 20: gate col (e==32) at q==0
            if (q == 0) {
#pragma unroll
                for (int mf = 0; mf < 2; mf++) {
                    int row0 = m0 + mf * 16 + (lane >> 2), row8 = row0 + 8;
                    float s0 = fmaf(fmaxf(C[mf][j][0] + r_bs1, 0.f), r_Ws2, r_bs2);
                    float s8 = fmaf(fmaxf(C[mf][j][2] + r_bs1, 0.f), r_Ws2, r_bs2);
                    sG[row0] = 1.f / (1.f + __expf(-s0));
                    sG[row8] = 1.f / (1.f + __expf(-s8));
                }
            }
        }
    }
    if (TBASE == 16) {              // the single constraint-carrying warp (nw 3)
#pragma unroll
        for (int i = 0; i < 4; i++) {
            cp[i] += __shfl_xor_sync(0xffffffffu, cp[i], 1);
            cp[i] += __shfl_xor_sync(0xffffffffu, cp[i], 2);
        }
        if ((lane & 3) == 0) {
#pragma unroll
            for (int i = 0; i < 4; i++) creg[i] += cp[i] + r_bc2;
        }
    }
}

// ======================= prep kernel: fp32 weights -> swizzled fp16 =======================
extern "C" __global__ void __launch_bounds__(256)
prep_kernel(const float* __restrict__ W1, const float* __restrict__ W2,
            const float* __restrict__ W3, const float* __restrict__ Wc1,
            const float* __restrict__ Ws1)
{
    int idx = blockIdx.x * 256 + threadIdx.x;
    if (idx < 81920) {
        int agent = idx / 10240;
        int rem = idx % 10240;
        int row = rem >> 5;
        int k = (rem & 31) * 4;
        const float* src; int n, N; u32 loff;
        if (row < 128)      { src = W1 + agent * 16384; n = row;       N = 128; loff = 0; }
        else if (row < 256) { src = W2 + agent * 16384; n = row - 128; N = 128; loff = 32768; }
        else                { src = W3 + agent * 8192;  n = row - 256; N = 64;  loff = 65536; }
        u32 h0 = pack_h(src[(k + 0) * N + n], src[(k + 1) * N + n]);
        u32 h1 = pack_h(src[(k + 2) * N + n], src[(k + 3) * N + n]);
        *(uint2*)(g_w + (u32)agent * 81920 + loff + plane_off(n, k)) = make_uint2(h0, h1);
    } else if (idx < 81920 + 1536) {
        int rem = idx - 81920;
        int row = rem >> 5;
        int k = (rem & 31) * 4;
        float w[4];
#pragma unroll
        for (int i = 0; i < 4; i++) {
            int kk = k + i;
            w[i] = (row < 32) ? __ldg(Wc1 + kk * 32 + row) : (row == 32 ? __ldg(Ws1 + kk) : 0.f);
        }
        *(uint2*)(g_ax + plane_off(row, k)) =
            make_uint2(pack_h(w[0], w[1]), pack_h(w[2], w[3]));
    }
}

// ======================= main kernel =======================
extern "C" __global__ void __launch_bounds__(256, 2)
qatten_mma(const float* __restrict__ states,
           const float* __restrict__ b1, const float* __restrict__ b2,
           const float* __restrict__ b3,
           const float* __restrict__ bs1, const float* __restrict__ Ws2,
           const float* __restrict__ bs2,
           const float* __restrict__ bc1, const float* __restrict__ Wc2,
           const float* __restrict__ bc2,
           float* __restrict__ out)
{
    extern __shared__ char smem[];
    const u32 sb = smem_u32(smem);
    const int tid = threadIdx.x;
    const int wid = tid >> 5, lane = tid & 31;
    const int b0 = blockIdx.x * BM;

    const int mq = wid & 1, nw = wid >> 1;   // 2 M-slices x 4 N-slices
    const int m0 = mq * 32;
    const int q = (lane & 3) * 2;

    float* sG  = (float*)(smem + SGOFF);
    float* sRd = (float*)(smem + SREDO);

    // ---- prologue: weights W1(0)+aux -> RW (async); states(0) regs -> convert -> P0 ----
    {
        for (int i = tid * 16; i < 32768; i += 4096) cp16(sb + RW + i, g_w + i);
        for (int i = tid * 16; i < 12288; i += 4096) cp16(sb + RW + 32768 + i, g_ax + i);
        cp_commit();                                        // [W1]
        float4 s[8];
        load_states_regs(s, states + (size_t)b0 * 128, tid);
        convert_regs(s, sb + RA, tid);
    }

    float oacc[2][2][4];
#pragma unroll
    for (int mf = 0; mf < 2; mf++)
#pragma unroll
        for (int j = 0; j < 2; j++)
#pragma unroll
            for (int i = 0; i < 4; i++) oacc[mf][j][i] = 0.f;
    float creg[4] = {0.f, 0.f, 0.f, 0.f};
    const float r_bs1 = __ldg(bs1), r_Ws2 = __ldg(Ws2), r_bs2 = __ldg(bs2), r_bc2 = __ldg(bc2);

    for (int n = 0; n < NAGENT; n++) {
        const u32 pin  = sb + ((n & 1) ? RB : RA);   // L1 input (states), L2 output, L3 input
        const u32 pmid = sb + ((n & 1) ? RA : RB);   // L1 output, L2 input, convert(n+1) dest

        // ---- L1 phase: weights ready + all prior smem writes visible ----
        cp_wait<0>();
        __syncthreads();
        {
            const float* b1n = b1 + n * 128;
            if (nw == 0) {
                float C[2][6][4];
                gemm2m<6>(C, pin, sb + RW, m0, 0, lane);
                __syncthreads();    // pin + RW consumed
                {   // stream W2 while epilogue runs
                    const unsigned char* src = g_w + (size_t)n * 81920 + 32768;
                    for (int i = tid * 16; i < 32768; i += 4096) cp16(sb + RW + i, src + i);
                    cp_commit();    // [W2]
                }
                epi_L1<6, 0>(C, pmid, b1n, bc1, Wc2, r_bs1, r_Ws2, r_bs2, r_bc2,
                             sG, creg, m0, lane, q);
            } else {
                float C[2][5][4];
                int tb = (nw == 1) ? 6 : (nw == 2 ? 11 : 16);
                gemm2m<5>(C, pin, sb + RW, m0, tb, lane);
                __syncthreads();
                {
                    const unsigned char* src = g_w + (size_t)n * 81920 + 32768;
                    for (int i = tid * 16; i < 32768; i += 4096) cp16(sb + RW + i, src + i);
                    cp_commit();    // [W2]
                }
                if (nw == 1)
                    epi_L1<5, 6>(C, pmid, b1n, bc1, Wc2, r_bs1, r_Ws2, r_bs2, r_bc2,
                                 sG, creg, m0, lane, q);
                else if (nw == 2)
                    epi_L1<5, 11>(C, pmid, b1n, bc1, Wc2, r_bs1, r_Ws2, r_bs2, r_bc2,
                                  sG, creg, m0, lane, q);
                else
                    epi_L1<5, 16>(C, pmid, b1n, bc1, Wc2, r_bs1, r_Ws2, r_bs2, r_bc2,
                                  sG, creg, m0, lane, q);
            }
        }
        cp_wait<0>();
        __syncthreads();

        // ---- L2: pmid @ W2 -> pin ----
        {
            float C[2][4][4];
            gemm2m<4>(C, pmid, sb + RW, m0, nw * 4, lane);
            __syncthreads();        // pmid + RW consumed
            {   // stream W3
                const unsigned char* src = g_w + (size_t)n * 81920 + 65536;
                for (int i = tid * 16; i < 16384; i += 4096) cp16(sb + RW + i, src + i);
                cp_commit();        // [W3]
            }
            const float* b2n = b2 + n * 128;
#pragma unroll
            for (int j = 0; j < 4; j++) {
                int tile = nw * 4 + j;
                int col = tile * 8 + q;
                float bx = __ldg(b2n + col), by = __ldg(b2n + col + 1);
#pragma unroll
                for (int mf = 0; mf < 2; mf++) {
                    int row0 = m0 + mf * 16 + (lane >> 2), row8 = row0 + 8;
                    u32 h0 = pack_h(fmaxf(C[mf][j][0] + bx, 0.f), fmaxf(C[mf][j][1] + by, 0.f));
                    u32 h2 = pack_h(fmaxf(C[mf][j][2] + bx, 0.f), fmaxf(C[mf][j][3] + by, 0.f));
                    u32 sw0 = ((u32)(((tile ^ row0) & 7) | (tile & 8))) << 4;
                    u32 sw8 = ((u32)(((tile ^ row8) & 7) | (tile & 8))) << 4;
                    asm volatile("st.shared.b32 [%0], %1;"
                        :: "r"(pin + (u32)row0 * 256 + sw0 + (u32)(q * 2)), "r"(h0));
                    asm volatile("st.shared.b32 [%0], %1;"
                        :: "r"(pin + (u32)row8 * 256 + sw8 + (u32)(q * 2)), "r"(h2));
                }
            }
        }
        cp_wait<0>();
        __syncthreads();

        // ---- L3: pin @ W3 -> oacc ; states(n+1) LDG+convert -> pmid hides under gemm ----
        {
            float4 s[8];
            if (n < NAGENT - 1)     // independent LDGs in flight during the GEMM
                load_states_regs(s, states + ((size_t)(n + 1) * BATCH + b0) * 128, tid);
            float C[2][2][4];
            gemm2m<2>(C, pin, sb + RW, m0, nw * 2, lane);
            if (n < NAGENT - 1)
                convert_regs(s, pmid, tid);   // pmid free (L2 consumed it)
            const float* b3n = b3 + n * 64;
#pragma unroll
            for (int mf = 0; mf < 2; mf++) {
                int row0 = m0 + mf * 16 + (lane >> 2), row8 = row0 + 8;
                float g0 = sG[row0], g8 = sG[row8];
#pragma unroll
                for (int j = 0; j < 2; j++) {
                    int col = (nw * 2 + j) * 8 + q;
                    float bx = __ldg(b3n + col), by = __ldg(b3n + col + 1);
                    oacc[mf][j][0] = fmaf(g0, C[mf][j][0] + bx, oacc[mf][j][0]);
                    oacc[mf][j][1] = fmaf(g0, C[mf][j][1] + by, oacc[mf][j][1]);
                    oacc[mf][j][2] = fmaf(g8, C[mf][j][2] + bx, oacc[mf][j][2]);
                    oacc[mf][j][3] = fmaf(g8, C[mf][j][3] + by, oacc[mf][j][3]);
                }
            }
            __syncthreads();        // pin + RW consumed; convert STS visible
            if (n < NAGENT - 1) {   // stream W1(n+1) (aux rows persist)
                const unsigned char* src = g_w + (size_t)(n + 1) * 81920;
                for (int i = tid * 16; i < 32768; i += 4096) cp16(sb + RW + i, src + i);
                cp_commit();        // [W1']
            }
        }
    }

    // ---- final: csum exchange + output ----
    if (nw == 3 && (lane & 3) == 0) {
#pragma unroll
        for (int i = 0; i < 4; i++) {
            int row = m0 + (i >> 1) * 16 + (i & 1) * 8 + (lane >> 2);
            sRd[row] = creg[i];
        }
    }
    __syncthreads();
#pragma unroll
    for (int mf = 0; mf < 2; mf++) {
#pragma unroll
        for (int h = 0; h < 2; h++) {
            int row = m0 + mf * 16 + h * 8 + (lane >> 2);
            float cs = sRd[row] * 0.125f;
#pragma unroll
            for (int j = 0; j < 2; j++) {
                int col = (nw * 2 + j) * 8 + q;
                float2 v;
                v.x = fmaf(oacc[mf][j][2 * h + 0], 0.125f, cs);
                v.y = fmaf(oacc[mf][j][2 * h + 1], 0.125f, cs);
                *(float2*)(out + (size_t)(b0 + row) * 64 + col) = v;
            }
        }
    }
}

extern "C" void kernel_launch(void* const* d_in, const int* in_sizes, int n_in,
                              void* d_out, int out_size)
{
    const float* states = (const float*)d_in[0];
    const float* W1  = (const float*)d_in[1];
    const float* b1  = (const float*)d_in[2];
    const float* W2  = (const float*)d_in[3];
    const float* b2  = (const float*)d_in[4];
    const float* W3  = (const float*)d_in[5];
    const float* b3  = (const float*)d_in[6];
    // d_in[7..12]: Wq1,bq1,Wq2,bq2,Wk,bk — dead (softmax rows sum to 1)
    const float* Ws1 = (const float*)d_in[13];
    const float* bs1 = (const float*)d_in[14];
    const float* Ws2 = (const float*)d_in[15];
    const float* bs2 = (const float*)d_in[16];
    const float* Wc1 = (const float*)d_in[17];
    const float* bc1 = (const float*)d_in[18];
    const float* Wc2 = (const float*)d_in[19];
    const float* bc2 = (const float*)d_in[20];
    float* out = (float*)d_out;

    prep_kernel<<<(81920 + 1536 + 255) / 256, 256>>>(W1, W2, W3, Wc1, Ws1);

    cudaFuncSetAttribute(qatten_mma,
                         cudaFuncAttributeMaxDynamicSharedMemorySize, SMEM_TOTAL);
    qatten_mma<<<BATCH / BM, 256, SMEM_TOTAL>>>(
        states, b1, b2, b3, bs1, Ws2, bs2, bc1, Wc2, bc2, out);
}